// round 4
// baseline (speedup 1.0000x reference)
#include <cuda_runtime.h>
#include <math.h>

// Problem constants
constexpr int H  = 256;
constexpr int B  = 4;
constexpr int S  = 128;
constexpr int T  = 128;
constexpr int DEPTH = 3;

// Scratch (device globals — no allocation allowed)
__device__ float g_pre_x[(size_t)B * S * T * H];   // 67 MB
__device__ float g_pre_y[(size_t)B * S * T * H];   // 67 MB
__device__ float g_hx  [(size_t)B * S * T * H];    // 67 MB
__device__ float g_hy  [(size_t)B * S * T * H];    // 67 MB
__device__ float g_psx [(size_t)B * S * H];        // depth-0 small pre (x)
__device__ float g_psy [(size_t)B * T * H];        // depth-0 small pre (y)

// Accurate tanh regardless of --use_fast_math (avoids MUFU.TANH's ~6e-4 abs err)
__device__ __forceinline__ float my_tanh(float x) {
    float ax = fabsf(x);
    float e  = expf(-2.0f * ax);          // fast-math __expf: ~1e-6 rel err here
    float t  = (1.0f - e) / (1.0f + e);
    return x < 0.0f ? -t : t;
}

// ---------------------------------------------------------------------------
// Prepass GEMM: C[m,n] = sum_k A[m,k] * W[n,k] + b1[n] + b2[n]
// N = K = 256 fixed. BM=BN=64, BK=32, 256 threads, 4x4 per thread, SW pipeline.
// ---------------------------------------------------------------------------
__global__ void __launch_bounds__(256) gemm256_bias(
    const float* __restrict__ A, const float* __restrict__ W,
    const float* __restrict__ b1, const float* __restrict__ b2,
    float* __restrict__ C)
{
    __shared__ float As[32][68];   // [k][m], stride 68 keeps 16B alignment
    __shared__ float Bs[32][68];   // [k][n]

    const int m0  = blockIdx.x << 6;
    const int n0  = blockIdx.y << 6;
    const int tid = threadIdx.x;
    const int tx  = tid & 15;       // n sub-tile
    const int ty  = tid >> 4;       // m sub-tile (0..15)
    const int lr  = tid >> 2;       // 0..63 load row
    const int lk  = (tid & 3) << 2; // 0,4,8,12

    const float* Ap = A + (size_t)(m0 + lr) * H + lk;
    const float* Wp = W + (size_t)(n0 + lr) * H + lk;

    float4 ra0 = *(const float4*)(Ap);
    float4 ra1 = *(const float4*)(Ap + 16);
    float4 rw0 = *(const float4*)(Wp);
    float4 rw1 = *(const float4*)(Wp + 16);

    float acc[4][4] = {};

    for (int c = 0; c < 8; c++) {
        As[lk + 0][lr] = ra0.x; As[lk + 1][lr] = ra0.y;
        As[lk + 2][lr] = ra0.z; As[lk + 3][lr] = ra0.w;
        As[lk + 16][lr] = ra1.x; As[lk + 17][lr] = ra1.y;
        As[lk + 18][lr] = ra1.z; As[lk + 19][lr] = ra1.w;
        Bs[lk + 0][lr] = rw0.x; Bs[lk + 1][lr] = rw0.y;
        Bs[lk + 2][lr] = rw0.z; Bs[lk + 3][lr] = rw0.w;
        Bs[lk + 16][lr] = rw1.x; Bs[lk + 17][lr] = rw1.y;
        Bs[lk + 18][lr] = rw1.z; Bs[lk + 19][lr] = rw1.w;
        __syncthreads();

        if (c < 7) {
            int k = (c + 1) << 5;
            ra0 = *(const float4*)(Ap + k);
            ra1 = *(const float4*)(Ap + k + 16);
            rw0 = *(const float4*)(Wp + k);
            rw1 = *(const float4*)(Wp + k + 16);
        }

        #pragma unroll
        for (int kk = 0; kk < 32; kk++) {
            float4 a = *(const float4*)&As[kk][ty << 2];
            float4 b = *(const float4*)&Bs[kk][tx << 2];
            acc[0][0] = fmaf(a.x, b.x, acc[0][0]);
            acc[0][1] = fmaf(a.x, b.y, acc[0][1]);
            acc[0][2] = fmaf(a.x, b.z, acc[0][2]);
            acc[0][3] = fmaf(a.x, b.w, acc[0][3]);
            acc[1][0] = fmaf(a.y, b.x, acc[1][0]);
            acc[1][1] = fmaf(a.y, b.y, acc[1][1]);
            acc[1][2] = fmaf(a.y, b.z, acc[1][2]);
            acc[1][3] = fmaf(a.y, b.w, acc[1][3]);
            acc[2][0] = fmaf(a.z, b.x, acc[2][0]);
            acc[2][1] = fmaf(a.z, b.y, acc[2][1]);
            acc[2][2] = fmaf(a.z, b.z, acc[2][2]);
            acc[2][3] = fmaf(a.z, b.w, acc[2][3]);
            acc[3][0] = fmaf(a.w, b.x, acc[3][0]);
            acc[3][1] = fmaf(a.w, b.y, acc[3][1]);
            acc[3][2] = fmaf(a.w, b.z, acc[3][2]);
            acc[3][3] = fmaf(a.w, b.w, acc[3][3]);
        }
        __syncthreads();
    }

    const int n = n0 + (tx << 2);
    float4 bv;
    bv.x = b1[n + 0] + b2[n + 0];
    bv.y = b1[n + 1] + b2[n + 1];
    bv.z = b1[n + 2] + b2[n + 2];
    bv.w = b1[n + 3] + b2[n + 3];

    #pragma unroll
    for (int i = 0; i < 4; i++) {
        int m = m0 + (ty << 2) + i;
        float4 o;
        o.x = acc[i][0] + bv.x;
        o.y = acc[i][1] + bv.y;
        o.z = acc[i][2] + bv.z;
        o.w = acc[i][3] + bv.w;
        *(float4*)(C + (size_t)m * H + n) = o;
    }
}

// ---------------------------------------------------------------------------
// Recurrent step. Both RNN paths in one launch (blockIdx.z selects path).
// out[p,n] = tanh(pre[p,n] + sum_k W[n,k] * state[p_mapped, k]),  p in [0,512)
// p = b*128 + q.  BM=32 (p), BN=64 (n), BK=32, 256 threads, 2x4 per thread.
// ---------------------------------------------------------------------------
struct PathArgs {
    const float* pre; int pre_sb; int pre_sq;
    const float* W;
    float*       out; int out_sb; int out_sq;
    const float* st;  int st_sb;  int st_sq;  int wrap;
};

__global__ void __launch_bounds__(256) step_kernel(PathArgs AX, PathArgs AY, int has_state)
{
    const PathArgs P = (blockIdx.z == 0) ? AX : AY;

    __shared__ float As[32][36];   // [k][p-local]
    __shared__ float Bs[32][68];   // [k][n-local]

    const int p0  = blockIdx.x << 5;
    const int n0  = blockIdx.y << 6;
    const int tid = threadIdx.x;
    const int tx  = tid & 15;      // n
    const int ty  = tid >> 4;      // p (0..15, 2 rows each)

    float acc[2][4] = {};

    if (has_state) {
        const int ar  = tid >> 3;        // 0..31 state row
        const int alk = (tid & 7) << 2;  // 0..28
        const int wr  = tid >> 2;        // 0..63 W row
        const int wlk = (tid & 3) << 2;  // 0..12

        {
            // nothing
        }
        int p  = p0 + ar;
        int b  = p >> 7;
        int q  = p & 127;
        int qm = P.wrap ? ((q + 127) & 127) : q;
        const float* Ap = P.st + (size_t)b * P.st_sb + (size_t)qm * P.st_sq + alk;
        const float* Wp = P.W + (size_t)(n0 + wr) * H + wlk;

        float4 ra  = *(const float4*)(Ap);
        float4 rw0 = *(const float4*)(Wp);
        float4 rw1 = *(const float4*)(Wp + 16);

        for (int c = 0; c < 8; c++) {
            As[alk + 0][ar] = ra.x; As[alk + 1][ar] = ra.y;
            As[alk + 2][ar] = ra.z; As[alk + 3][ar] = ra.w;
            Bs[wlk + 0][wr] = rw0.x; Bs[wlk + 1][wr] = rw0.y;
            Bs[wlk + 2][wr] = rw0.z; Bs[wlk + 3][wr] = rw0.w;
            Bs[wlk + 16][wr] = rw1.x; Bs[wlk + 17][wr] = rw1.y;
            Bs[wlk + 18][wr] = rw1.z; Bs[wlk + 19][wr] = rw1.w;
            __syncthreads();

            if (c < 7) {
                int k = (c + 1) << 5;
                ra  = *(const float4*)(Ap + k);
                rw0 = *(const float4*)(Wp + k);
                rw1 = *(const float4*)(Wp + k + 16);
            }

            #pragma unroll
            for (int kk = 0; kk < 32; kk++) {
                float2 a  = *(const float2*)&As[kk][ty << 1];
                float4 bb = *(const float4*)&Bs[kk][tx << 2];
                acc[0][0] = fmaf(a.x, bb.x, acc[0][0]);
                acc[0][1] = fmaf(a.x, bb.y, acc[0][1]);
                acc[0][2] = fmaf(a.x, bb.z, acc[0][2]);
                acc[0][3] = fmaf(a.x, bb.w, acc[0][3]);
                acc[1][0] = fmaf(a.y, bb.x, acc[1][0]);
                acc[1][1] = fmaf(a.y, bb.y, acc[1][1]);
                acc[1][2] = fmaf(a.y, bb.z, acc[1][2]);
                acc[1][3] = fmaf(a.y, bb.w, acc[1][3]);
            }
            __syncthreads();
        }
    }

    #pragma unroll
    for (int i = 0; i < 2; i++) {
        int p = p0 + (ty << 1) + i;
        int b = p >> 7;
        int q = p & 127;
        int n = n0 + (tx << 2);
        float4 pv = *(const float4*)(P.pre + (size_t)b * P.pre_sb + (size_t)q * P.pre_sq + n);
        float4 o;
        o.x = my_tanh(acc[i][0] + pv.x);
        o.y = my_tanh(acc[i][1] + pv.y);
        o.z = my_tanh(acc[i][2] + pv.z);
        o.w = my_tanh(acc[i][3] + pv.w);
        *(float4*)(P.out + (size_t)b * P.out_sb + (size_t)q * P.out_sq + n) = o;
    }
}

// ---------------------------------------------------------------------------
// Host orchestration: per depth, 1-2 prepass GEMMs + 128 fused step launches.
// All on the default stream (graph-capturable, no allocs, no syncs).
// ---------------------------------------------------------------------------
extern "C" void kernel_launch(void* const* d_in, const int* in_sizes, int n_in,
                              void* d_out, int out_size)
{
    const float* src   = (const float*)d_in[0];
    const float* trg   = (const float*)d_in[1];
    const float* Wx_ih = (const float*)d_in[2];
    const float* Wx_hh = (const float*)d_in[3];
    const float* bx_ih = (const float*)d_in[4];
    const float* bx_hh = (const float*)d_in[5];
    const float* Wy_ih = (const float*)d_in[6];
    const float* Wy_hh = (const float*)d_in[7];
    const float* by_ih = (const float*)d_in[8];
    const float* by_hh = (const float*)d_in[9];
    float* out = (float*)d_out;

    float *pre_x, *pre_y, *hx, *hy, *psx, *psy;
    cudaGetSymbolAddress((void**)&pre_x, g_pre_x);
    cudaGetSymbolAddress((void**)&pre_y, g_pre_y);
    cudaGetSymbolAddress((void**)&hx,    g_hx);
    cudaGetSymbolAddress((void**)&hy,    g_hy);
    cudaGetSymbolAddress((void**)&psx,   g_psx);
    cudaGetSymbolAddress((void**)&psy,   g_psy);

    const dim3 stepGrid(16, 4, 2);   // 512/32 p-tiles, 256/64 n-tiles, 2 paths

    for (int d = 0; d < DEPTH; d++) {
        // ---- prepass: input projection + fused biases ----
        if (d == 0) {
            // inputs are broadcasts: only B*S (resp. B*T) unique rows
            gemm256_bias<<<dim3(B * S / 64, H / 64), 256>>>(
                src, Wx_ih, bx_ih, bx_hh, psx);
            gemm256_bias<<<dim3(B * T / 64, H / 64), 256>>>(
                trg, Wy_ih, by_ih, by_hh, psy);
        } else {
            gemm256_bias<<<dim3(B * S * T / 64, H / 64), 256>>>(
                hx, Wx_ih + (size_t)d * H * H, bx_ih + d * H, bx_hh + d * H, pre_x);
            gemm256_bias<<<dim3(B * S * T / 64, H / 64), 256>>>(
                hy, Wy_ih + (size_t)d * H * H, by_ih + d * H, by_hh + d * H, pre_y);
        }

        // ---- output placement: final depth writes d_out interleaved ----
        const int   OS = (d == 2) ? 2 * H : H;          // per-(i,j) row stride
        float* Ox = (d == 2) ? out       : hx;          // slot 0
        float* Oy = (d == 2) ? out + H   : hy;          // slot 1

        for (int st = 0; st < S; st++) {
            PathArgs AX, AY;

            // x-path: step index i = st, parallel q = j, state at (i-1, (j-1)%T)
            AX.W      = Wx_hh + (size_t)d * H * H;
            AX.out    = Ox + (size_t)st * T * OS;
            AX.out_sb = S * T * OS;  AX.out_sq = OS;
            AX.st     = Ox + (size_t)(st - 1) * T * OS;  // unused when st==0
            AX.st_sb  = S * T * OS;  AX.st_sq  = OS;  AX.wrap = 1;
            if (d == 0) { AX.pre = psx + (size_t)st * H;        AX.pre_sb = S * H;     AX.pre_sq = 0; }
            else        { AX.pre = pre_x + (size_t)st * T * H;  AX.pre_sb = S * T * H; AX.pre_sq = H; }

            // y-path: step index j = st, parallel q = i, state at (i, j-1)
            AY.W      = Wy_hh + (size_t)d * H * H;
            AY.out    = Oy + (size_t)st * OS;
            AY.out_sb = S * T * OS;  AY.out_sq = T * OS;
            AY.st     = Oy + (size_t)(st - 1) * OS;      // unused when st==0
            AY.st_sb  = S * T * OS;  AY.st_sq  = T * OS;  AY.wrap = 0;
            if (d == 0) { AY.pre = psy + (size_t)st * H;   AY.pre_sb = T * H;     AY.pre_sq = 0; }
            else        { AY.pre = pre_y + (size_t)st * H; AY.pre_sb = S * T * H; AY.pre_sq = T * H; }

            step_kernel<<<stepGrid, 256>>>(AX, AY, st > 0);
        }
    }
}